// round 9
// baseline (speedup 1.0000x reference)
#include <cuda_runtime.h>
#include <math.h>

#define B 8
#define N 256
#define D 128
#define H 256
#define BN (B * N)   // 2048

// Scratch (allocation-free rule: device globals), 16B aligned for vector access
__device__ __align__(16) float g_hi[BN * H];   // slots @ W_m1[:D]
__device__ __align__(16) float g_hj[BN * H];   // slots @ W_m1[D:] + b_m1
__device__ __align__(16) float g_G [BN * H];   // sum_j a_ij * gelu(hi_i + hj_j)

__device__ __forceinline__ float gelu_exact(float x) {
    return 0.5f * x * (1.0f + erff(x * 0.70710678118654752440f));
}

// 2*gelu(x) via A&S 7.1.28 with 1/sqrt2 folded into coefficients:
//   P = 1 + b1'|x| + ... + b6'|x|^6,   erf(|x|/sqrt2) = 1 - P^-16
//   P^-16 = ex2(-16*lg2(P))
//   2*gelu(x) = (x + |x|) - |x| * P^-16
// Scalar fp32: |x| and -|x| are free SASS operand modifiers; no packing movs.
__device__ __forceinline__ float gelu2_fast(float x) {
    const float ax = fabsf(x);
    float p = fmaf(5.38297500e-6f, ax, 4.88897213e-5f);   // b6', b5'
    p = fmaf(p, ax, 3.80035750e-5f);                      // b4'
    p = fmaf(p, ax, 3.27762714e-3f);                      // b3'
    p = fmaf(p, ax, 2.11410062e-2f);                      // b2'
    p = fmaf(p, ax, 4.98677908e-2f);                      // b1'
    p = fmaf(p, ax, 1.0f);                                // P
    float l; asm("lg2.approx.f32 %0,%1;" : "=f"(l) : "f"(p));
    l *= -16.0f;                                          // FMUL-imm, rt=1
    float e; asm("ex2.approx.f32 %0,%1;" : "=f"(e) : "f"(l));
    return fmaf(-ax, e, x + ax);
}

// ---------------------------------------------------------------------------
// Kernel 1: proj GEMM, 64x64 tiles (grid 32x8 = 256 blocks), 256 threads.
// Thread owns 4 rows x 4 cols = 16 acc. Combined output [hi|hj] is (BN) x 512.
// ---------------------------------------------------------------------------
#define KC 32
__global__ __launch_bounds__(256) void proj_kernel(
    const float* __restrict__ slots, const float* __restrict__ W_m1,
    const float* __restrict__ b_m1)
{
    const int r0   = blockIdx.x * 64;        // row-block base (b*N + n)
    const int part = blockIdx.y >> 2;        // 0 -> hi, 1 -> hj
    const int c0   = (blockIdx.y & 3) * 64;  // column base within 256-wide half
    const int tid  = threadIdx.x;
    const int ty   = tid >> 4, tx = tid & 15;

    __shared__ float As[64][KC + 1];         // pad -> conflict-free col reads
    __shared__ float Ws[KC][65];

    float acc[4][4];
#pragma unroll
    for (int r = 0; r < 4; ++r)
#pragma unroll
        for (int c = 0; c < 4; ++c) acc[r][c] = 0.f;

    const float* wsrc = W_m1 + (size_t)(part * D) * H + c0;

    for (int kc = 0; kc < D; kc += KC) {
#pragma unroll
        for (int l = 0; l < 8; ++l) {
            const int idx = tid + l * 256;
            const int r = idx >> 5, k = idx & 31;
            As[r][k] = slots[(r0 + r) * D + kc + k];
        }
#pragma unroll
        for (int l = 0; l < 8; ++l) {
            const int idx = tid + l * 256;
            const int k = idx >> 6, c = idx & 63;
            Ws[k][c] = wsrc[(kc + k) * H + c];
        }
        __syncthreads();

#pragma unroll
        for (int k = 0; k < KC; ++k) {
            float wv[4], av[4];
#pragma unroll
            for (int c = 0; c < 4; ++c) wv[c] = Ws[k][tx + 16 * c];
#pragma unroll
            for (int r = 0; r < 4; ++r) av[r] = As[ty + 16 * r][k];
#pragma unroll
            for (int r = 0; r < 4; ++r)
#pragma unroll
                for (int c = 0; c < 4; ++c)
                    acc[r][c] = fmaf(av[r], wv[c], acc[r][c]);
        }
        __syncthreads();
    }

    if (part == 0) {
#pragma unroll
        for (int r = 0; r < 4; ++r)
#pragma unroll
            for (int c = 0; c < 4; ++c)
                g_hi[(size_t)(r0 + ty + 16 * r) * H + c0 + tx + 16 * c] = acc[r][c];
    } else {
        float bm[4];
#pragma unroll
        for (int c = 0; c < 4; ++c) bm[c] = b_m1[c0 + tx + 16 * c];
#pragma unroll
        for (int r = 0; r < 4; ++r)
#pragma unroll
            for (int c = 0; c < 4; ++c)
                g_hj[(size_t)(r0 + ty + 16 * r) * H + c0 + tx + 16 * c] = acc[r][c] + bm[c];
    }
}

// ---------------------------------------------------------------------------
// Kernel 2 (dominant): G[b,i,h] = sum_j a[b,i,j] * gelu(hi[b,i,h] + hjp[b,j,h])
// 2 i-rows per block (grid 1024), 128 threads; thread owns h-pair (2t, 2t+1),
// all-scalar fp32 math (4 independent gelu chains per j for ILP).
// ---------------------------------------------------------------------------
__global__ __launch_bounds__(128) void msg_agg_kernel(
    const float* __restrict__ adj)
{
    const int row0 = blockIdx.x * 2;        // global row = b*N + i
    const int b    = row0 >> 8;
    const int i0   = row0 & (N - 1);
    const int tid  = threadIdx.x;           // h-pair = (2*tid, 2*tid+1)

    __shared__ float a_s[2][N];             // prescaled by 0.5 (gelu2 = 2*gelu)
    const float* adj_b = adj + ((size_t)b * N + i0) * N;
#pragma unroll
    for (int idx = tid; idx < 2 * N; idx += 128)
        ((float*)a_s)[idx] = 0.5f * adj_b[idx];
    __syncthreads();

    const float2* hj2 = (const float2*)(g_hj + (size_t)b * N * H) + tid;
    const float2 hi0 = ((const float2*)(g_hi + (size_t) row0      * H))[tid];
    const float2 hi1 = ((const float2*)(g_hi + (size_t)(row0 + 1) * H))[tid];

    float acc00 = 0.f, acc01 = 0.f, acc10 = 0.f, acc11 = 0.f;

#pragma unroll 4
    for (int j = 0; j < N; ++j) {
        const float2 hj = hj2[(size_t)j * (H / 2)];
        const float a0 = a_s[0][j];
        const float a1 = a_s[1][j];
        acc00 = fmaf(a0, gelu2_fast(hi0.x + hj.x), acc00);
        acc01 = fmaf(a0, gelu2_fast(hi0.y + hj.y), acc01);
        acc10 = fmaf(a1, gelu2_fast(hi1.x + hj.x), acc10);
        acc11 = fmaf(a1, gelu2_fast(hi1.y + hj.y), acc11);
    }

    float2 o0; o0.x = acc00; o0.y = acc01;
    float2 o1; o1.x = acc10; o1.y = acc11;
    ((float2*)(g_G + (size_t) row0      * H))[tid] = o0;
    ((float2*)(g_G + (size_t)(row0 + 1) * H))[tid] = o1;
}

// ---------------------------------------------------------------------------
// Kernel 3: fused epilogue. 8 rows per block, 512 threads (grid 256).
//   agg = G @ W_m2 + rowsum(a)*b_m2
//   u   = slots@W_u1[:D] + agg@W_u1[D:] + b_u1 ; LayerNorm ; gelu
//   out = slots + u @ W_u2 + b_u2
// ---------------------------------------------------------------------------
__global__ __launch_bounds__(512) void epilogue_kernel(
    const float* __restrict__ slots, const float* __restrict__ adj,
    const float* __restrict__ W_m2, const float* __restrict__ b_m2,
    const float* __restrict__ W_u1, const float* __restrict__ b_u1,
    const float* __restrict__ ln_g, const float* __restrict__ ln_b,
    const float* __restrict__ W_u2, const float* __restrict__ b_u2,
    float* __restrict__ out)
{
    const int R  = 8;
    const int r0 = blockIdx.x * R;          // global row = b*N + n
    const int b  = r0 >> 8;
    const int n0 = r0 & (N - 1);
    const int tid = threadIdx.x;
    const int warp = tid >> 5, lane = tid & 31;

    __shared__ float buf_s[R][H];           // G tile, later reused as u tile
    __shared__ float s_s [R][D];
    __shared__ float agg_s[R][D];
    __shared__ float asum_s[R];
    __shared__ float mu_s[R], rstd_s[R];

    for (int idx = tid; idx < R * H; idx += 512)
        ((float*)buf_s)[idx] = g_G[r0 * H + idx];
    for (int idx = tid; idx < R * D; idx += 512)
        ((float*)s_s)[idx] = slots[r0 * D + idx];

    // adjacency row sums: warps 0..7 handle rows 0..7
    if (warp < R) {
        const float* arow = adj + ((size_t)b * N + n0 + warp) * N;
        float s = 0.f;
#pragma unroll
        for (int k = 0; k < 8; ++k) s += arow[lane + k * 32];
#pragma unroll
        for (int o = 16; o > 0; o >>= 1) s += __shfl_xor_sync(~0u, s, o);
        if (lane == 0) asum_s[warp] = s;
    }
    __syncthreads();

    // aggregated = G @ W_m2 + asum * b_m2
    {
        const int d  = tid & (D - 1);
        const int rb = (tid >> 7) * 2;       // rows rb, rb+1
        float acc[2];
        const float bm2 = b_m2[d];
#pragma unroll
        for (int r = 0; r < 2; ++r) acc[r] = asum_s[rb + r] * bm2;
#pragma unroll 8
        for (int hh = 0; hh < H; ++hh) {
            const float w = W_m2[hh * D + d];
#pragma unroll
            for (int r = 0; r < 2; ++r)
                acc[r] = fmaf(buf_s[rb + r][hh], w, acc[r]);
        }
        __syncthreads();                     // all reads of buf_s-as-G done
#pragma unroll
        for (int r = 0; r < 2; ++r) agg_s[rb + r][d] = acc[r];
    }
    __syncthreads();

    // u = slots@W_u1[:D] + agg@W_u1[D:] + b_u1   (overwrite buf_s)
    {
        const int h  = tid & 255;
        const int g  = tid >> 8;             // 0,1 -> rows 4g..4g+3
        float acc[4];
        const float bu = b_u1[h];
#pragma unroll
        for (int r = 0; r < 4; ++r) acc[r] = bu;
#pragma unroll 8
        for (int d = 0; d < D; ++d) {
            const float w1 = W_u1[d * H + h];
            const float w2 = W_u1[(D + d) * H + h];
#pragma unroll
            for (int r = 0; r < 4; ++r) {
                acc[r] = fmaf(s_s[4 * g + r][d], w1, acc[r]);
                acc[r] = fmaf(agg_s[4 * g + r][d], w2, acc[r]);
            }
        }
#pragma unroll
        for (int r = 0; r < 4; ++r) buf_s[4 * g + r][h] = acc[r];
    }
    __syncthreads();

    // LayerNorm stats: warps 0..7, one row each (two-pass)
    if (warp < R) {
        const int r = warp;
        float s = 0.f;
#pragma unroll
        for (int k = 0; k < 8; ++k) s += buf_s[r][lane + k * 32];
#pragma unroll
        for (int o = 16; o > 0; o >>= 1) s += __shfl_xor_sync(~0u, s, o);
        const float mu = s * (1.f / H);
        float ss = 0.f;
#pragma unroll
        for (int k = 0; k < 8; ++k) {
            const float v = buf_s[r][lane + k * 32] - mu;
            ss += v * v;
        }
#pragma unroll
        for (int o = 16; o > 0; o >>= 1) ss += __shfl_xor_sync(~0u, ss, o);
        if (lane == 0) {
            mu_s[r]   = mu;
            rstd_s[r] = rsqrtf(ss * (1.f / H) + 1e-5f);
        }
    }
    __syncthreads();

    // normalize + gelu (in place)
    {
        const int h = tid & 255;
        const int g = tid >> 8;
        const float gg = ln_g[h], bb = ln_b[h];
#pragma unroll
        for (int r = 0; r < 4; ++r) {
            const int rr = 4 * g + r;
            const float v = (buf_s[rr][h] - mu_s[rr]) * rstd_s[rr] * gg + bb;
            buf_s[rr][h] = gelu_exact(v);
        }
    }
    __syncthreads();

    // out = slots + u @ W_u2 + b_u2
    {
        const int d  = tid & (D - 1);
        const int rb = (tid >> 7) * 2;
        float acc[2];
        const float bu2 = b_u2[d];
#pragma unroll
        for (int r = 0; r < 2; ++r) acc[r] = bu2;
#pragma unroll 8
        for (int hh = 0; hh < H; ++hh) {
            const float w = W_u2[hh * D + d];
#pragma unroll
            for (int r = 0; r < 2; ++r)
                acc[r] = fmaf(buf_s[rb + r][hh], w, acc[r]);
        }
#pragma unroll
        for (int r = 0; r < 2; ++r)
            out[(r0 + rb + r) * D + d] = s_s[rb + r][d] + acc[r];
    }
}

// ---------------------------------------------------------------------------
extern "C" void kernel_launch(void* const* d_in, const int* in_sizes, int n_in,
                              void* d_out, int out_size)
{
    const float* slots = (const float*)d_in[0];
    const float* adj   = (const float*)d_in[1];
    const float* W_m1  = (const float*)d_in[2];
    const float* b_m1  = (const float*)d_in[3];
    const float* W_m2  = (const float*)d_in[4];
    const float* b_m2  = (const float*)d_in[5];
    const float* W_u1  = (const float*)d_in[6];
    const float* b_u1  = (const float*)d_in[7];
    const float* ln_g  = (const float*)d_in[8];
    const float* ln_b  = (const float*)d_in[9];
    const float* W_u2  = (const float*)d_in[10];
    const float* b_u2  = (const float*)d_in[11];
    float* out = (float*)d_out;

    dim3 pg(BN / 64, 8);
    proj_kernel<<<pg, 256>>>(slots, W_m1, b_m1);
    msg_agg_kernel<<<BN / 2, 128>>>(adj);
    epilogue_kernel<<<BN / 8, 512>>>(slots, adj, W_m2, b_m2, W_u1, b_u1,
                                     ln_g, ln_b, W_u2, b_u2, out);
}

// round 10
// speedup vs baseline: 1.4453x; 1.4453x over previous
#include <cuda_runtime.h>
#include <math.h>

#define B 8
#define N 256
#define D 128
#define H 256
#define BN (B * N)   // 2048

// Scratch (allocation-free rule: device globals), 16B aligned for vector access
__device__ __align__(16) float g_hi[BN * H];   // slots @ W_m1[:D]
__device__ __align__(16) float g_hj[BN * H];   // slots @ W_m1[D:] + b_m1
__device__ __align__(16) float g_G [BN * H];   // sum_j a_ij * gelu(hi_i + hj_j)
__device__ float g_asum[BN];                   // rowsum(adjacency)

__device__ __forceinline__ float gelu_exact(float x) {
    return 0.5f * x * (1.0f + erff(x * 0.70710678118654752440f));
}

// 2*gelu(x) via the tanh formulation + MUFU tanh.approx (sm_75+):
//   2*gelu(x) ~= x * (1 + tanh(0.7978845608*(x + 0.044715 x^3)))
// 6 FFMA-class ops + 1 MUFU per element (incl. the accumulate done by caller).
__device__ __forceinline__ float gelu2_tanh(float x) {
    const float xx = x * x;
    const float inner = fmaf(0.0356774081f, xx, 0.7978845608f); // sqrt(2/pi)*(1 + 0.044715 x^2)
    const float w = x * inner;
    float t; asm("tanh.approx.f32 %0,%1;" : "=f"(t) : "f"(w));
    return fmaf(x, t, x);                                        // x*(1+t)
}

// ---------------------------------------------------------------------------
// Kernel 0: adjacency row sums (for epilogue's b_m2 term). Warp per row.
// ---------------------------------------------------------------------------
__global__ __launch_bounds__(256) void asum_kernel(const float* __restrict__ adj)
{
    const int row  = blockIdx.x * 8 + (threadIdx.x >> 5);  // b*N + n
    const int lane = threadIdx.x & 31;
    const float* arow = adj + (size_t)row * N;
    float s = 0.f;
#pragma unroll
    for (int k = 0; k < 8; ++k) s += arow[lane + k * 32];
#pragma unroll
    for (int o = 16; o > 0; o >>= 1) s += __shfl_xor_sync(~0u, s, o);
    if (lane == 0) g_asum[row] = s;
}

// ---------------------------------------------------------------------------
// Kernel 1: proj GEMM, 64x32 tiles (grid 32x16 = 512 blocks), 256 threads.
// Thread owns 4 rows x 2 cols = 8 acc (~40 regs) -> good occupancy.
// Combined output [hi|hj] is (BN) x 512. K chunked at 32.
// ---------------------------------------------------------------------------
#define KC 32
__global__ __launch_bounds__(256) void proj_kernel(
    const float* __restrict__ slots, const float* __restrict__ W_m1,
    const float* __restrict__ b_m1)
{
    const int r0   = blockIdx.x * 64;        // row-block base (b*N + n)
    const int part = blockIdx.y >> 3;        // 0 -> hi, 1 -> hj
    const int c0   = (blockIdx.y & 7) * 32;  // column base within 256-wide half
    const int tid  = threadIdx.x;
    const int ty   = tid >> 4, tx = tid & 15;

    __shared__ float As[64][KC + 1];         // pad -> conflict-free col reads
    __shared__ float Ws[KC][33];

    float acc[4][2];
#pragma unroll
    for (int r = 0; r < 4; ++r)
#pragma unroll
        for (int c = 0; c < 2; ++c) acc[r][c] = 0.f;

    const float* wsrc = W_m1 + (size_t)(part * D) * H + c0;

    for (int kc = 0; kc < D; kc += KC) {
        // A chunk: 64 x 32 = 2048 elems, 8/thread, coalesced 32-wide rows
#pragma unroll
        for (int l = 0; l < 8; ++l) {
            const int idx = tid + l * 256;
            const int r = idx >> 5, k = idx & 31;
            As[r][k] = slots[(r0 + r) * D + kc + k];
        }
        // W chunk: 32 x 32 = 1024 elems, 4/thread, coalesced 32-wide rows
#pragma unroll
        for (int l = 0; l < 4; ++l) {
            const int idx = tid + l * 256;
            const int k = idx >> 5, c = idx & 31;
            Ws[k][c] = wsrc[(kc + k) * H + c];
        }
        __syncthreads();

#pragma unroll
        for (int k = 0; k < KC; ++k) {
            float wv[2], av[4];
#pragma unroll
            for (int c = 0; c < 2; ++c) wv[c] = Ws[k][tx + 16 * c];
#pragma unroll
            for (int r = 0; r < 4; ++r) av[r] = As[ty + 16 * r][k];
#pragma unroll
            for (int r = 0; r < 4; ++r)
#pragma unroll
                for (int c = 0; c < 2; ++c)
                    acc[r][c] = fmaf(av[r], wv[c], acc[r][c]);
        }
        __syncthreads();
    }

    if (part == 0) {
#pragma unroll
        for (int r = 0; r < 4; ++r)
#pragma unroll
            for (int c = 0; c < 2; ++c)
                g_hi[(size_t)(r0 + ty + 16 * r) * H + c0 + tx + 16 * c] = acc[r][c];
    } else {
        float bm[2];
#pragma unroll
        for (int c = 0; c < 2; ++c) bm[c] = b_m1[c0 + tx + 16 * c];
#pragma unroll
        for (int r = 0; r < 4; ++r)
#pragma unroll
            for (int c = 0; c < 2; ++c)
                g_hj[(size_t)(r0 + ty + 16 * r) * H + c0 + tx + 16 * c] = acc[r][c] + bm[c];
    }
}

// ---------------------------------------------------------------------------
// Kernel 2 (dominant): G[b,i,h] = sum_j a[b,i,j] * gelu(hi[b,i,h] + hjp[b,j,h])
// 2 i-rows per block (grid 1024), 128 threads; thread owns h-pair (2t, 2t+1).
// tanh-based gelu: 6 FFMA-class + 1 MUFU per element, 4 independent chains.
// ---------------------------------------------------------------------------
__global__ __launch_bounds__(128) void msg_agg_kernel(
    const float* __restrict__ adj)
{
    const int row0 = blockIdx.x * 2;        // global row = b*N + i
    const int b    = row0 >> 8;
    const int i0   = row0 & (N - 1);
    const int tid  = threadIdx.x;           // h-pair = (2*tid, 2*tid+1)

    __shared__ float a_s[2][N];             // prescaled by 0.5 (gelu2 = 2*gelu)
    const float* adj_b = adj + ((size_t)b * N + i0) * N;
#pragma unroll
    for (int idx = tid; idx < 2 * N; idx += 128)
        ((float*)a_s)[idx] = 0.5f * adj_b[idx];
    __syncthreads();

    const float2* hj2 = (const float2*)(g_hj + (size_t)b * N * H) + tid;
    const float2 hi0 = ((const float2*)(g_hi + (size_t) row0      * H))[tid];
    const float2 hi1 = ((const float2*)(g_hi + (size_t)(row0 + 1) * H))[tid];

    float acc00 = 0.f, acc01 = 0.f, acc10 = 0.f, acc11 = 0.f;

#pragma unroll 4
    for (int j = 0; j < N; ++j) {
        const float2 hj = hj2[(size_t)j * (H / 2)];
        const float a0 = a_s[0][j];
        const float a1 = a_s[1][j];
        acc00 = fmaf(a0, gelu2_tanh(hi0.x + hj.x), acc00);
        acc01 = fmaf(a0, gelu2_tanh(hi0.y + hj.y), acc01);
        acc10 = fmaf(a1, gelu2_tanh(hi1.x + hj.x), acc10);
        acc11 = fmaf(a1, gelu2_tanh(hi1.y + hj.y), acc11);
    }

    float2 o0; o0.x = acc00; o0.y = acc01;
    float2 o1; o1.x = acc10; o1.y = acc11;
    ((float2*)(g_G + (size_t) row0      * H))[tid] = o0;
    ((float2*)(g_G + (size_t)(row0 + 1) * H))[tid] = o1;
}

// ---------------------------------------------------------------------------
// Kernel 3: fused epilogue. 8 rows per block, 512 threads (grid 256).
//   agg = G @ W_m2 + g_asum*b_m2
//   u   = slots@W_u1[:D] + agg@W_u1[D:] + b_u1 ; LayerNorm ; gelu
//   out = slots + u @ W_u2 + b_u2
// ---------------------------------------------------------------------------
__global__ __launch_bounds__(512) void epilogue_kernel(
    const float* __restrict__ slots,
    const float* __restrict__ W_m2, const float* __restrict__ b_m2,
    const float* __restrict__ W_u1, const float* __restrict__ b_u1,
    const float* __restrict__ ln_g, const float* __restrict__ ln_b,
    const float* __restrict__ W_u2, const float* __restrict__ b_u2,
    float* __restrict__ out)
{
    const int R  = 8;
    const int r0 = blockIdx.x * R;          // global row = b*N + n
    const int tid = threadIdx.x;
    const int warp = tid >> 5, lane = tid & 31;

    __shared__ float buf_s[R][H];           // G tile, later reused as u tile
    __shared__ float s_s [R][D];
    __shared__ float agg_s[R][D];
    __shared__ float asum_s[R];
    __shared__ float mu_s[R], rstd_s[R];

    for (int idx = tid; idx < R * H; idx += 512)
        ((float*)buf_s)[idx] = g_G[r0 * H + idx];
    for (int idx = tid; idx < R * D; idx += 512)
        ((float*)s_s)[idx] = slots[r0 * D + idx];
    if (tid < R) asum_s[tid] = g_asum[r0 + tid];
    __syncthreads();

    // aggregated = G @ W_m2 + asum * b_m2
    {
        const int d  = tid & (D - 1);
        const int rb = (tid >> 7) * 2;       // rows rb, rb+1
        float acc[2];
        const float bm2 = b_m2[d];
#pragma unroll
        for (int r = 0; r < 2; ++r) acc[r] = asum_s[rb + r] * bm2;
#pragma unroll 8
        for (int hh = 0; hh < H; ++hh) {
            const float w = W_m2[hh * D + d];
#pragma unroll
            for (int r = 0; r < 2; ++r)
                acc[r] = fmaf(buf_s[rb + r][hh], w, acc[r]);
        }
        __syncthreads();                     // all reads of buf_s-as-G done
#pragma unroll
        for (int r = 0; r < 2; ++r) agg_s[rb + r][d] = acc[r];
    }
    __syncthreads();

    // u = slots@W_u1[:D] + agg@W_u1[D:] + b_u1   (overwrite buf_s)
    {
        const int h  = tid & 255;
        const int g  = tid >> 8;             // 0,1 -> rows 4g..4g+3
        float acc[4];
        const float bu = b_u1[h];
#pragma unroll
        for (int r = 0; r < 4; ++r) acc[r] = bu;
#pragma unroll 8
        for (int d = 0; d < D; ++d) {
            const float w1 = W_u1[d * H + h];
            const float w2 = W_u1[(D + d) * H + h];
#pragma unroll
            for (int r = 0; r < 4; ++r) {
                acc[r] = fmaf(s_s[4 * g + r][d], w1, acc[r]);
                acc[r] = fmaf(agg_s[4 * g + r][d], w2, acc[r]);
            }
        }
#pragma unroll
        for (int r = 0; r < 4; ++r) buf_s[4 * g + r][h] = acc[r];
    }
    __syncthreads();

    // LayerNorm stats: warps 0..7, one row each (two-pass)
    if (warp < R) {
        const int r = warp;
        float s = 0.f;
#pragma unroll
        for (int k = 0; k < 8; ++k) s += buf_s[r][lane + k * 32];
#pragma unroll
        for (int o = 16; o > 0; o >>= 1) s += __shfl_xor_sync(~0u, s, o);
        const float mu = s * (1.f / H);
        float ss = 0.f;
#pragma unroll
        for (int k = 0; k < 8; ++k) {
            const float v = buf_s[r][lane + k * 32] - mu;
            ss += v * v;
        }
#pragma unroll
        for (int o = 16; o > 0; o >>= 1) ss += __shfl_xor_sync(~0u, ss, o);
        if (lane == 0) {
            mu_s[r]   = mu;
            rstd_s[r] = rsqrtf(ss * (1.f / H) + 1e-5f);
        }
    }
    __syncthreads();

    // normalize + gelu (in place) — exact erf gelu here (only 0.5M evals)
    {
        const int h = tid & 255;
        const int g = tid >> 8;
        const float gg = ln_g[h], bb = ln_b[h];
#pragma unroll
        for (int r = 0; r < 4; ++r) {
            const int rr = 4 * g + r;
            const float v = (buf_s[rr][h] - mu_s[rr]) * rstd_s[rr] * gg + bb;
            buf_s[rr][h] = gelu_exact(v);
        }
    }
    __syncthreads();

    // out = slots + u @ W_u2 + b_u2
    {
        const int d  = tid & (D - 1);
        const int rb = (tid >> 7) * 2;
        float acc[2];
        const float bu2 = b_u2[d];
#pragma unroll
        for (int r = 0; r < 2; ++r) acc[r] = bu2;
#pragma unroll 8
        for (int hh = 0; hh < H; ++hh) {
            const float w = W_u2[hh * D + d];
#pragma unroll
            for (int r = 0; r < 2; ++r)
                acc[r] = fmaf(buf_s[rb + r][hh], w, acc[r]);
        }
#pragma unroll
        for (int r = 0; r < 2; ++r)
            out[(r0 + rb + r) * D + d] = s_s[rb + r][d] + acc[r];
    }
}

// ---------------------------------------------------------------------------
extern "C" void kernel_launch(void* const* d_in, const int* in_sizes, int n_in,
                              void* d_out, int out_size)
{
    const float* slots = (const float*)d_in[0];
    const float* adj   = (const float*)d_in[1];
    const float* W_m1  = (const float*)d_in[2];
    const float* b_m1  = (const float*)d_in[3];
    const float* W_m2  = (const float*)d_in[4];
    const float* b_m2  = (const float*)d_in[5];
    const float* W_u1  = (const float*)d_in[6];
    const float* b_u1  = (const float*)d_in[7];
    const float* ln_g  = (const float*)d_in[8];
    const float* ln_b  = (const float*)d_in[9];
    const float* W_u2  = (const float*)d_in[10];
    const float* b_u2  = (const float*)d_in[11];
    float* out = (float*)d_out;

    asum_kernel<<<BN / 8, 256>>>(adj);
    dim3 pg(BN / 64, 16);
    proj_kernel<<<pg, 256>>>(slots, W_m1, b_m1);
    msg_agg_kernel<<<BN / 2, 128>>>(adj);
    epilogue_kernel<<<BN / 8, 512>>>(slots, W_m2, b_m2, W_u1, b_u1,
                                     ln_g, ln_b, W_u2, b_u2, out);
}

// round 11
// speedup vs baseline: 1.4483x; 1.0020x over previous
#include <cuda_runtime.h>
#include <math.h>

#define B 8
#define N 256
#define D 128
#define H 256
#define BN (B * N)   // 2048

// Scratch (allocation-free rule: device globals), 16B aligned for vector access
__device__ __align__(16) float g_hi[BN * H];   // slots @ W_m1[:D]
__device__ __align__(16) float g_hj[BN * H];   // slots @ W_m1[D:] + b_m1
__device__ __align__(16) float g_G [BN * H];   // sum_j a_ij * gelu(hi_i + hj_j)
__device__ float g_asum[BN];                   // rowsum(adjacency)

__device__ __forceinline__ float gelu_exact(float x) {
    return 0.5f * x * (1.0f + erff(x * 0.70710678118654752440f));
}

// 2*gelu(x) via the tanh formulation + MUFU tanh.approx (sm_75+):
//   2*gelu(x) ~= x * (1 + tanh(0.7978845608*(x + 0.044715 x^3)))
__device__ __forceinline__ float gelu2_tanh(float x) {
    const float xx = x * x;
    const float inner = fmaf(0.0356774081f, xx, 0.7978845608f);
    const float w = x * inner;
    float t; asm("tanh.approx.f32 %0,%1;" : "=f"(t) : "f"(w));
    return fmaf(x, t, x);                                        // x*(1+t)
}

// ---------------------------------------------------------------------------
// Kernel 0: adjacency row sums (for epilogue's b_m2 term). Warp per row.
// ---------------------------------------------------------------------------
__global__ __launch_bounds__(256) void asum_kernel(const float* __restrict__ adj)
{
    const int row  = blockIdx.x * 8 + (threadIdx.x >> 5);  // b*N + n
    const int lane = threadIdx.x & 31;
    const float* arow = adj + (size_t)row * N;
    float s = 0.f;
#pragma unroll
    for (int k = 0; k < 8; ++k) s += arow[lane + k * 32];
#pragma unroll
    for (int o = 16; o > 0; o >>= 1) s += __shfl_xor_sync(~0u, s, o);
    if (lane == 0) g_asum[row] = s;
}

// ---------------------------------------------------------------------------
// Kernel 1: proj GEMM, 64x32 tiles (grid 32x16 = 512 blocks), 256 threads.
// ---------------------------------------------------------------------------
#define KC 32
__global__ __launch_bounds__(256) void proj_kernel(
    const float* __restrict__ slots, const float* __restrict__ W_m1,
    const float* __restrict__ b_m1)
{
    const int r0   = blockIdx.x * 64;        // row-block base (b*N + n)
    const int part = blockIdx.y >> 3;        // 0 -> hi, 1 -> hj
    const int c0   = (blockIdx.y & 7) * 32;  // column base within 256-wide half
    const int tid  = threadIdx.x;
    const int ty   = tid >> 4, tx = tid & 15;

    __shared__ float As[64][KC + 1];
    __shared__ float Ws[KC][33];

    float acc[4][2];
#pragma unroll
    for (int r = 0; r < 4; ++r)
#pragma unroll
        for (int c = 0; c < 2; ++c) acc[r][c] = 0.f;

    const float* wsrc = W_m1 + (size_t)(part * D) * H + c0;

    for (int kc = 0; kc < D; kc += KC) {
#pragma unroll
        for (int l = 0; l < 8; ++l) {
            const int idx = tid + l * 256;
            const int r = idx >> 5, k = idx & 31;
            As[r][k] = slots[(r0 + r) * D + kc + k];
        }
#pragma unroll
        for (int l = 0; l < 4; ++l) {
            const int idx = tid + l * 256;
            const int k = idx >> 5, c = idx & 31;
            Ws[k][c] = wsrc[(kc + k) * H + c];
        }
        __syncthreads();

#pragma unroll
        for (int k = 0; k < KC; ++k) {
            float wv[2], av[4];
#pragma unroll
            for (int c = 0; c < 2; ++c) wv[c] = Ws[k][tx + 16 * c];
#pragma unroll
            for (int r = 0; r < 4; ++r) av[r] = As[ty + 16 * r][k];
#pragma unroll
            for (int r = 0; r < 4; ++r)
#pragma unroll
                for (int c = 0; c < 2; ++c)
                    acc[r][c] = fmaf(av[r], wv[c], acc[r][c]);
        }
        __syncthreads();
    }

    if (part == 0) {
#pragma unroll
        for (int r = 0; r < 4; ++r)
#pragma unroll
            for (int c = 0; c < 2; ++c)
                g_hi[(size_t)(r0 + ty + 16 * r) * H + c0 + tx + 16 * c] = acc[r][c];
    } else {
        float bm[2];
#pragma unroll
        for (int c = 0; c < 2; ++c) bm[c] = b_m1[c0 + tx + 16 * c];
#pragma unroll
        for (int r = 0; r < 4; ++r)
#pragma unroll
            for (int c = 0; c < 2; ++c)
                g_hj[(size_t)(r0 + ty + 16 * r) * H + c0 + tx + 16 * c] = acc[r][c] + bm[c];
    }
}

// ---------------------------------------------------------------------------
// Kernel 2: G[b,i,h] = sum_j a[b,i,j] * gelu(hi[b,i,h] + hjp[b,j,h])
// 2 i-rows per block (grid 1024), 128 threads; thread owns h-pair (2t, 2t+1).
// tanh-based gelu: 6 FFMA-class + 1 MUFU per element, 4 independent chains.
// ---------------------------------------------------------------------------
__global__ __launch_bounds__(128) void msg_agg_kernel(
    const float* __restrict__ adj)
{
    const int row0 = blockIdx.x * 2;        // global row = b*N + i
    const int b    = row0 >> 8;
    const int i0   = row0 & (N - 1);
    const int tid  = threadIdx.x;           // h-pair = (2*tid, 2*tid+1)

    __shared__ float a_s[2][N];             // prescaled by 0.5 (gelu2 = 2*gelu)
    const float* adj_b = adj + ((size_t)b * N + i0) * N;
#pragma unroll
    for (int idx = tid; idx < 2 * N; idx += 128)
        ((float*)a_s)[idx] = 0.5f * adj_b[idx];
    __syncthreads();

    const float2* hj2 = (const float2*)(g_hj + (size_t)b * N * H) + tid;
    const float2 hi0 = ((const float2*)(g_hi + (size_t) row0      * H))[tid];
    const float2 hi1 = ((const float2*)(g_hi + (size_t)(row0 + 1) * H))[tid];

    float acc00 = 0.f, acc01 = 0.f, acc10 = 0.f, acc11 = 0.f;

#pragma unroll 4
    for (int j = 0; j < N; ++j) {
        const float2 hj = hj2[(size_t)j * (H / 2)];
        const float a0 = a_s[0][j];
        const float a1 = a_s[1][j];
        acc00 = fmaf(a0, gelu2_tanh(hi0.x + hj.x), acc00);
        acc01 = fmaf(a0, gelu2_tanh(hi0.y + hj.y), acc01);
        acc10 = fmaf(a1, gelu2_tanh(hi1.x + hj.x), acc10);
        acc11 = fmaf(a1, gelu2_tanh(hi1.y + hj.y), acc11);
    }

    float2 o0; o0.x = acc00; o0.y = acc01;
    float2 o1; o1.x = acc10; o1.y = acc11;
    ((float2*)(g_G + (size_t) row0      * H))[tid] = o0;
    ((float2*)(g_G + (size_t)(row0 + 1) * H))[tid] = o1;
}

// ---------------------------------------------------------------------------
// Kernel 3: fused epilogue. R=4 rows per block, 256 threads, grid 512
// (the R3-measured config; the R=8/512-thread variant profiled at 64us).
//   agg = G @ W_m2 + g_asum*b_m2
//   u   = slots@W_u1[:D] + agg@W_u1[D:] + b_u1 ; LayerNorm ; gelu
//   out = slots + u @ W_u2 + b_u2
// ---------------------------------------------------------------------------
__global__ __launch_bounds__(256) void epilogue_kernel(
    const float* __restrict__ slots,
    const float* __restrict__ W_m2, const float* __restrict__ b_m2,
    const float* __restrict__ W_u1, const float* __restrict__ b_u1,
    const float* __restrict__ ln_g, const float* __restrict__ ln_b,
    const float* __restrict__ W_u2, const float* __restrict__ b_u2,
    float* __restrict__ out)
{
    const int R  = 4;
    const int r0 = blockIdx.x * R;          // global row = b*N + n
    const int tid = threadIdx.x;
    const int warp = tid >> 5, lane = tid & 31;

    __shared__ float buf_s[R][H];           // G tile, later reused as u tile
    __shared__ float s_s [R][D];
    __shared__ float agg_s[R][D];
    __shared__ float asum_s[R];
    __shared__ float mu_s[R], rstd_s[R];

    for (int idx = tid; idx < R * H; idx += 256)
        ((float*)buf_s)[idx] = g_G[r0 * H + idx];
    for (int idx = tid; idx < R * D; idx += 256)
        ((float*)s_s)[idx] = slots[r0 * D + idx];
    if (tid < R) asum_s[tid] = g_asum[r0 + tid];
    __syncthreads();

    // aggregated = G @ W_m2 + asum * b_m2
    {
        const int d  = tid & (D - 1);
        const int rb = (tid >> 7) * 2;       // rows rb, rb+1
        float acc[2];
        const float bm2 = b_m2[d];
#pragma unroll
        for (int r = 0; r < 2; ++r) acc[r] = asum_s[rb + r] * bm2;
#pragma unroll 8
        for (int hh = 0; hh < H; ++hh) {
            const float w = W_m2[hh * D + d];
#pragma unroll
            for (int r = 0; r < 2; ++r)
                acc[r] = fmaf(buf_s[rb + r][hh], w, acc[r]);
        }
        __syncthreads();                     // all reads of buf_s-as-G done
#pragma unroll
        for (int r = 0; r < 2; ++r) agg_s[rb + r][d] = acc[r];
    }
    __syncthreads();

    // u = slots@W_u1[:D] + agg@W_u1[D:] + b_u1   (overwrite buf_s)
    {
        const int h = tid;
        float acc[R];
        const float bu = b_u1[h];
#pragma unroll
        for (int r = 0; r < R; ++r) acc[r] = bu;
#pragma unroll 8
        for (int d = 0; d < D; ++d) {
            const float w1 = W_u1[d * H + h];
            const float w2 = W_u1[(D + d) * H + h];
#pragma unroll
            for (int r = 0; r < R; ++r) {
                acc[r] = fmaf(s_s[r][d], w1, acc[r]);
                acc[r] = fmaf(agg_s[r][d], w2, acc[r]);
            }
        }
#pragma unroll
        for (int r = 0; r < R; ++r) buf_s[r][h] = acc[r];
    }
    __syncthreads();

    // LayerNorm stats: warps 0..3, one row each (two-pass)
    if (warp < R) {
        const int r = warp;
        float s = 0.f;
#pragma unroll
        for (int k = 0; k < 8; ++k) s += buf_s[r][lane + k * 32];
#pragma unroll
        for (int o = 16; o > 0; o >>= 1) s += __shfl_xor_sync(~0u, s, o);
        const float mu = s * (1.f / H);
        float ss = 0.f;
#pragma unroll
        for (int k = 0; k < 8; ++k) {
            const float v = buf_s[r][lane + k * 32] - mu;
            ss += v * v;
        }
#pragma unroll
        for (int o = 16; o > 0; o >>= 1) ss += __shfl_xor_sync(~0u, ss, o);
        if (lane == 0) {
            mu_s[r]   = mu;
            rstd_s[r] = rsqrtf(ss * (1.f / H) + 1e-5f);
        }
    }
    __syncthreads();

    // normalize + gelu (in place) — exact erf gelu (only 0.5M evals)
    {
        const int h = tid;
        const float gg = ln_g[h], bb = ln_b[h];
#pragma unroll
        for (int r = 0; r < R; ++r) {
            const float v = (buf_s[r][h] - mu_s[r]) * rstd_s[r] * gg + bb;
            buf_s[r][h] = gelu_exact(v);
        }
    }
    __syncthreads();

    // out = slots + u @ W_u2 + b_u2
    {
        const int d  = tid & (D - 1);
        const int rb = (tid >> 7) * 2;
        float acc[2];
        const float bu2 = b_u2[d];
#pragma unroll
        for (int r = 0; r < 2; ++r) acc[r] = bu2;
#pragma unroll 8
        for (int hh = 0; hh < H; ++hh) {
            const float w = W_u2[hh * D + d];
#pragma unroll
            for (int r = 0; r < 2; ++r)
                acc[r] = fmaf(buf_s[rb + r][hh], w, acc[r]);
        }
#pragma unroll
        for (int r = 0; r < 2; ++r)
            out[(r0 + rb + r) * D + d] = s_s[rb + r][d] + acc[r];
    }
}

// ---------------------------------------------------------------------------
extern "C" void kernel_launch(void* const* d_in, const int* in_sizes, int n_in,
                              void* d_out, int out_size)
{
    const float* slots = (const float*)d_in[0];
    const float* adj   = (const float*)d_in[1];
    const float* W_m1  = (const float*)d_in[2];
    const float* b_m1  = (const float*)d_in[3];
    const float* W_m2  = (const float*)d_in[4];
    const float* b_m2  = (const float*)d_in[5];
    const float* W_u1  = (const float*)d_in[6];
    const float* b_u1  = (const float*)d_in[7];
    const float* ln_g  = (const float*)d_in[8];
    const float* ln_b  = (const float*)d_in[9];
    const float* W_u2  = (const float*)d_in[10];
    const float* b_u2  = (const float*)d_in[11];
    float* out = (float*)d_out;

    asum_kernel<<<BN / 8, 256>>>(adj);
    dim3 pg(BN / 64, 16);
    proj_kernel<<<pg, 256>>>(slots, W_m1, b_m1);
    msg_agg_kernel<<<BN / 2, 128>>>(adj);
    epilogue_kernel<<<BN / 4, 256>>>(slots, W_m2, b_m2, W_u1, b_u1,
                                     ln_g, ln_b, W_u2, b_u2, out);
}